// round 15
// baseline (speedup 1.0000x reference)
#include <cuda_runtime.h>
#include <math.h>

// ---------------------------------------------------------------------------
// MiniStageGRU on GB300 (sm_103a). Conv-GRU, convs (2,5), pad H(1,0) W(2,2).
// B=16, Cin_x=4, C=8, T=1000, F=257.
//
// Round-15 = round-14 (592.6us: FP=272, 8co x 4f co-paired f32x2 tile,
// __constant__ weights via LDCU; k2 fully software-pipelined at (256,2);
// float4 pad_all) + ONE change:
//   - k3 PARTIAL pipeline at (256,3): prefetch next ci's xp row-pair only
//     (16 regs), rh loaded inline -> ~80 regs, 3 blocks/SM retained.
// ---------------------------------------------------------------------------

typedef unsigned long long ULL;

static __device__ __forceinline__ ULL pk(float lo, float hi) {
    ULL r;
    asm("mov.b64 %0, {%1,%2};" : "=l"(r) : "f"(lo), "f"(hi));
    return r;
}
static __device__ __forceinline__ void upk(ULL v, float& lo, float& hi) {
    asm("mov.b64 {%0,%1}, %2;" : "=f"(lo), "=f"(hi) : "l"(v));
}
static __device__ __forceinline__ ULL ffma2(ULL a, ULL b, ULL c) {
    ULL d;
    asm("fma.rn.f32x2 %0, %1, %2, %3;" : "=l"(d) : "l"(a), "l"(b), "l"(c));
    return d;
}
static __device__ __forceinline__ float sigf(float x) {
    return __fdividef(1.0f, 1.0f + __expf(-x));
}
static __device__ __forceinline__ float tanh_fast(float x) {
    return __fdividef(2.0f, 1.0f + __expf(-2.0f * x)) - 1.0f;
}

constexpr int B    = 16;
constexpr int C    = 8;
constexpr int CIX  = 4;
constexpr int T    = 1000;
constexpr int TP1  = 1001;          // T+1 rows, row 0 = zeros
constexpr int F    = 257;
constexpr int FP   = 272;           // [2 left pad][257 data][13 right pad]
constexpr int CH   = TP1 * FP;
constexpr int FBLK = 65;

constexpr int NTHREAD_MAIN = B * T * FBLK;

// ---- packed-weight layout (ULL units) ---------------------------------------
constexpr int R1      = 0;          // K1: pre weights + bias
constexpr int L1_B    = 160;
constexpr int R1_N    = 164;
constexpr int R2      = R1_N;       // K2: xz, xr, hz, hr + biases
constexpr int L_XZ    = R2 + 0;
constexpr int L_XR    = R2 + 320;
constexpr int L_HZ    = R2 + 640;
constexpr int L_HR    = R2 + 960;
constexpr int L_BZ    = R2 + 1280;
constexpr int L_BR    = R2 + 1284;
constexpr int R2_N    = 1288;
constexpr int R3      = R2 + R2_N;  // K3: xn, hn + bias
constexpr int L_XN    = R3 + 0;
constexpr int L_HN    = R3 + 320;
constexpr int L_BN    = R3 + 640;
constexpr int R3_N    = 644;
constexpr int WPK_N   = R3 + R3_N;  // 2096

// ---- device scratch (+CH slack on arrays that get prefetched) ----------------
__device__ __align__(16) ULL   g_wpk[WPK_N];
__constant__ __align__(16) ULL c_wpk[WPK_N];
__device__ __align__(16) float g_xpad[(size_t)B * CIX * CH];
__device__ __align__(16) float g_hpad[(size_t)B * C   * CH + CH];
__device__ __align__(16) float g_xp  [(size_t)B * C   * CH + CH];
__device__ __align__(16) float g_z   [(size_t)B * C   * CH];
__device__ __align__(16) float g_rh  [(size_t)B * C   * CH];

// ---- weight packing: f32x2 co-pairs {w[2p], w[2p+1]} --------------------------
__global__ void prep_pack(const float* __restrict__ pre_w, const float* __restrict__ pre_b,
                          const float* __restrict__ xz_w,  const float* __restrict__ xz_b,
                          const float* __restrict__ xr_w,  const float* __restrict__ xr_b,
                          const float* __restrict__ xn_w,  const float* __restrict__ xn_b,
                          const float* __restrict__ hz_w,  const float* __restrict__ hz_b,
                          const float* __restrict__ hr_w,  const float* __restrict__ hr_b,
                          const float* __restrict__ hn_w,  const float* __restrict__ hn_b)
{
    int i = blockIdx.x * blockDim.x + threadIdx.x;
    if (i >= WPK_N) return;
    ULL v;
    if (i < L1_B) {                                    // pre weights (CIN=4)
        int r = i; int p = r & 3; int s = r >> 2;
        int kw = s % 5; s /= 5; int kh = s & 1; int ci = s >> 1;
        v = pk(pre_w[((2 * p)     * CIX + ci) * 10 + kh * 5 + kw],
               pre_w[((2 * p + 1) * CIX + ci) * 10 + kh * 5 + kw]);
    } else if (i < R1_N) {
        int p = i - L1_B;
        v = pk(pre_b[2 * p], pre_b[2 * p + 1]);
    } else if (i < L_BZ) {                             // xz/xr/hz/hr weights
        int j = i - R2;
        int gi = j / 320, r = j % 320;
        int p = r & 3; int s = r >> 2;
        int kw = s % 5; s /= 5; int kh = s & 1; int ci = s >> 1;
        const float* w = (gi == 0) ? xz_w : (gi == 1) ? xr_w : (gi == 2) ? hz_w : hr_w;
        v = pk(w[((2 * p)     * C + ci) * 10 + kh * 5 + kw],
               w[((2 * p + 1) * C + ci) * 10 + kh * 5 + kw]);
    } else if (i < L_BR) {
        int p = i - L_BZ;
        v = pk(xz_b[2 * p] + hz_b[2 * p], xz_b[2 * p + 1] + hz_b[2 * p + 1]);
    } else if (i < R3) {
        int p = i - L_BR;
        v = pk(xr_b[2 * p] + hr_b[2 * p], xr_b[2 * p + 1] + hr_b[2 * p + 1]);
    } else if (i < L_BN) {                             // xn/hn weights
        int j = i - R3;
        int gi = j / 320, r = j % 320;
        int p = r & 3; int s = r >> 2;
        int kw = s % 5; s /= 5; int kh = s & 1; int ci = s >> 1;
        const float* w = gi ? hn_w : xn_w;
        v = pk(w[((2 * p)     * C + ci) * 10 + kh * 5 + kw],
               w[((2 * p + 1) * C + ci) * 10 + kh * 5 + kw]);
    } else {
        int p = i - L_BN;
        v = pk(xn_b[2 * p] + hn_b[2 * p], xn_b[2 * p + 1] + hn_b[2 * p + 1]);
    }
    g_wpk[i] = v;
}

// ---- conv row micro-kernels: window by VALUE, weights from __constant__ ------
static __device__ __forceinline__ void conv_rowv(
    float4 A, float4 Bv, int woff, ULL acc[4][4])
{
    float win[8] = {A.x, A.y, A.z, A.w, Bv.x, Bv.y, Bv.z, Bv.w};
    ULL wb[8];
#pragma unroll
    for (int m = 0; m < 8; ++m) wb[m] = pk(win[m], win[m]);
#pragma unroll
    for (int kw = 0; kw < 5; ++kw) {
        ULL w0 = c_wpk[woff + kw * 4 + 0];
        ULL w1 = c_wpk[woff + kw * 4 + 1];
        ULL w2 = c_wpk[woff + kw * 4 + 2];
        ULL w3 = c_wpk[woff + kw * 4 + 3];
#pragma unroll
        for (int j = 0; j < 4; ++j) {
            acc[0][j] = ffma2(w0, wb[j + kw], acc[0][j]);
            acc[1][j] = ffma2(w1, wb[j + kw], acc[1][j]);
            acc[2][j] = ffma2(w2, wb[j + kw], acc[2][j]);
            acc[3][j] = ffma2(w3, wb[j + kw], acc[3][j]);
        }
    }
}

static __device__ __forceinline__ void conv_row_dualv(
    float4 A, float4 Bv, int woff1, int woff2,
    ULL a1[4][4], ULL a2[4][4])
{
    float win[8] = {A.x, A.y, A.z, A.w, Bv.x, Bv.y, Bv.z, Bv.w};
    ULL wb[8];
#pragma unroll
    for (int m = 0; m < 8; ++m) wb[m] = pk(win[m], win[m]);
#pragma unroll
    for (int kw = 0; kw < 5; ++kw) {
        ULL u0 = c_wpk[woff1 + kw * 4 + 0];
        ULL u1 = c_wpk[woff1 + kw * 4 + 1];
        ULL u2 = c_wpk[woff1 + kw * 4 + 2];
        ULL u3 = c_wpk[woff1 + kw * 4 + 3];
        ULL v0 = c_wpk[woff2 + kw * 4 + 0];
        ULL v1 = c_wpk[woff2 + kw * 4 + 1];
        ULL v2 = c_wpk[woff2 + kw * 4 + 2];
        ULL v3 = c_wpk[woff2 + kw * 4 + 3];
#pragma unroll
        for (int j = 0; j < 4; ++j) {
            a1[0][j] = ffma2(u0, wb[j + kw], a1[0][j]);
            a1[1][j] = ffma2(u1, wb[j + kw], a1[1][j]);
            a1[2][j] = ffma2(u2, wb[j + kw], a1[2][j]);
            a1[3][j] = ffma2(u3, wb[j + kw], a1[3][j]);
            a2[0][j] = ffma2(v0, wb[j + kw], a2[0][j]);
            a2[1][j] = ffma2(v1, wb[j + kw], a2[1][j]);
            a2[2][j] = ffma2(v2, wb[j + kw], a2[2][j]);
            a2[3][j] = ffma2(v3, wb[j + kw], a2[3][j]);
        }
    }
}

static __device__ __forceinline__ float4 ld4(const float* p) {
    return *reinterpret_cast<const float4*>(p);
}
static __device__ __forceinline__ void st2(float* p, float a, float b) {
    *reinterpret_cast<float2*>(p) = make_float2(a, b);
}

// ---- fused pad kernel (float4 quads): x, h, zero-row-0 of intermediates -------
constexpr int PAD_QX = B * CIX * CH / 4;
constexpr int PAD_QH = B * C * CH / 4;
__global__ void pad_all(const float* __restrict__ x, const float* __restrict__ h) {
    int g = blockIdx.x * blockDim.x + threadIdx.x;
    if (g < PAD_QX) {
        int e0 = g * 4;
        int fm = e0 % FP;
        int r  = e0 / FP;
        int tr = r % TP1;
        int bc = r / TP1;
        float4 v = make_float4(0.f, 0.f, 0.f, 0.f);
        if (tr > 0) {
            const float* srow = x + (bc * T + tr - 1) * F;
            int f0 = fm - 2;
            if (f0 >= 0 && f0 < F)         v.x = srow[f0];
            if (f0 + 1 >= 0 && f0 + 1 < F) v.y = srow[f0 + 1];
            if (f0 + 2 >= 0 && f0 + 2 < F) v.z = srow[f0 + 2];
            if (f0 + 3 >= 0 && f0 + 3 < F) v.w = srow[f0 + 3];
        }
        *reinterpret_cast<float4*>(g_xpad + e0) = v;
    } else if (g < PAD_QX + PAD_QH) {
        int e0 = (g - PAD_QX) * 4;
        int fm = e0 % FP;
        int r  = e0 / FP;
        int tr = r % TP1;
        int bc = r / TP1;
        float4 v = make_float4(0.f, 0.f, 0.f, 0.f);
        if (tr > 0) {
            const float* srow = h + (bc * T + tr - 1) * F;
            int f0 = fm - 2;
            if (f0 >= 0 && f0 < F)         v.x = srow[f0];
            if (f0 + 1 >= 0 && f0 + 1 < F) v.y = srow[f0 + 1];
            if (f0 + 2 >= 0 && f0 + 2 < F) v.z = srow[f0 + 2];
            if (f0 + 3 >= 0 && f0 + 3 < F) v.w = srow[f0 + 3];
        } else {
            *reinterpret_cast<float4*>(g_xp + e0) = v;
            *reinterpret_cast<float4*>(g_rh + e0) = v;
        }
        *reinterpret_cast<float4*>(g_hpad + e0) = v;
    }
}

// ---- K1: xp = elu(conv(x, pre)) -----------------------------------------------
__global__ void __launch_bounds__(256, 4) k1_pre() {
    int g = blockIdx.x * 256 + threadIdx.x;
    if (g >= NTHREAD_MAIN) return;
    const int fb = g % FBLK; int r1 = g / FBLK;
    const int t = r1 % T, b = r1 / T;
    const int f0 = fb * 4;

    ULL acc[4][4];
#pragma unroll
    for (int p = 0; p < 4; ++p) {
        ULL bb = c_wpk[L1_B + p];
#pragma unroll
        for (int j = 0; j < 4; ++j) acc[p][j] = bb;
    }

    int o = (b * CIX) * CH + t * FP + f0;
#pragma unroll
    for (int ci = 0; ci < CIX; ++ci) {
        const float* r0 = g_xpad + o;
        float4 a0 = ld4(r0),      a1 = ld4(r0 + 4);
        float4 b0 = ld4(r0 + FP), b1 = ld4(r0 + FP + 4);
        conv_rowv(a0, a1, R1 + ci * 40,      acc);
        conv_rowv(b0, b1, R1 + ci * 40 + 20, acc);
        o += CH;
    }

    const bool lastfb = (fb == FBLK - 1);
#pragma unroll
    for (int p = 0; p < 4; ++p) {
        float* rowA = g_xp + (b * C + 2 * p)     * CH + (t + 1) * FP + 2 + f0;
        float* rowB = g_xp + (b * C + 2 * p + 1) * CH + (t + 1) * FP + 2 + f0;
        float v[2][4];
#pragma unroll
        for (int j = 0; j < 4; ++j) {
            float lo, hi;
            upk(acc[p][j], lo, hi);
            lo = lo > 0.0f ? lo : (__expf(lo) - 1.0f);
            hi = hi > 0.0f ? hi : (__expf(hi) - 1.0f);
            bool valid = (f0 + j) < F;
            v[0][j] = valid ? lo : 0.0f;
            v[1][j] = valid ? hi : 0.0f;
        }
        st2(rowA,     v[0][0], v[0][1]); st2(rowA + 2, v[0][2], v[0][3]);
        st2(rowB,     v[1][0], v[1][1]); st2(rowB + 2, v[1][2], v[1][3]);
        if (fb == 0) { st2(rowA - 2, 0.f, 0.f); st2(rowB - 2, 0.f, 0.f); }
        if (lastfb) {
#pragma unroll
            for (int q = 4; q < 14; q += 2) { st2(rowA + q, 0.f, 0.f); st2(rowB + q, 0.f, 0.f); }
        }
    }
}

// ---- K2: z and r*h (fully software-pipelined ci loop) --------------------------
__global__ void __launch_bounds__(256, 2) k2_zr() {
    int g = blockIdx.x * 256 + threadIdx.x;
    if (g >= NTHREAD_MAIN) return;
    const int fb = g % FBLK; int r1 = g / FBLK;
    const int t = r1 % T, b = r1 / T;
    const int f0 = fb * 4;

    ULL az[4][4], ar[4][4];
#pragma unroll
    for (int p = 0; p < 4; ++p) {
        ULL bz = c_wpk[L_BZ + p], br = c_wpk[L_BR + p];
#pragma unroll
        for (int j = 0; j < 4; ++j) { az[p][j] = bz; ar[p][j] = br; }
    }

    int o = (b * C) * CH + t * FP + f0;
    float4 xa0 = ld4(g_xp + o),        xa1 = ld4(g_xp + o + 4);
    float4 xb0 = ld4(g_xp + o + FP),   xb1 = ld4(g_xp + o + FP + 4);
    float4 ha0 = ld4(g_hpad + o),      ha1 = ld4(g_hpad + o + 4);
    float4 hb0 = ld4(g_hpad + o + FP), hb1 = ld4(g_hpad + o + FP + 4);

    int wo = 0;
#pragma unroll 2
    for (int ci = 0; ci < C; ++ci) {
        float4 cxa0 = xa0, cxa1 = xa1, cxb0 = xb0, cxb1 = xb1;
        float4 cha0 = ha0, cha1 = ha1, chb0 = hb0, chb1 = hb1;
        o += CH;
        xa0 = ld4(g_xp + o);        xa1 = ld4(g_xp + o + 4);
        xb0 = ld4(g_xp + o + FP);   xb1 = ld4(g_xp + o + FP + 4);
        ha0 = ld4(g_hpad + o);      ha1 = ld4(g_hpad + o + 4);
        hb0 = ld4(g_hpad + o + FP); hb1 = ld4(g_hpad + o + FP + 4);
        conv_row_dualv(cxa0, cxa1, L_XZ + wo,      L_XR + wo,      az, ar);
        conv_row_dualv(cxb0, cxb1, L_XZ + wo + 20, L_XR + wo + 20, az, ar);
        conv_row_dualv(cha0, cha1, L_HZ + wo,      L_HR + wo,      az, ar);
        conv_row_dualv(chb0, chb1, L_HZ + wo + 20, L_HR + wo + 20, az, ar);
        wo += 40;
    }

    const bool lastfb = (fb == FBLK - 1);
#pragma unroll
    for (int p = 0; p < 4; ++p) {
        float zv[2][4], rv[2][4];
#pragma unroll
        for (int j = 0; j < 4; ++j) {
            float a, bb;
            upk(az[p][j], a, bb); zv[0][j] = sigf(a); zv[1][j] = sigf(bb);
            upk(ar[p][j], a, bb); rv[0][j] = sigf(a); rv[1][j] = sigf(bb);
        }
#pragma unroll
        for (int half = 0; half < 2; ++half) {
            const int co = 2 * p + half;
            const int ro = (b * C + co) * CH + (t + 1) * FP + 2 + f0;
            const float* hrow = g_hpad + ro;
            float* zrow  = g_z  + ro;
            float* rhrow = g_rh + ro;
            float2 h01 = *reinterpret_cast<const float2*>(hrow);
            float2 h23 = *reinterpret_cast<const float2*>(hrow + 2);
            st2(zrow,      zv[half][0], zv[half][1]);
            st2(zrow + 2,  zv[half][2], zv[half][3]);
            st2(rhrow,     rv[half][0] * h01.x, rv[half][1] * h01.y);
            st2(rhrow + 2, rv[half][2] * h23.x, rv[half][3] * h23.y);
            if (fb == 0) st2(rhrow - 2, 0.f, 0.f);
            if (lastfb) {
#pragma unroll
                for (int q = 4; q < 14; q += 2) st2(rhrow + q, 0.f, 0.f);
            }
        }
    }
}

// ---- K3: n + output (partial pipeline: xp prefetched, rh inline) -----------------
__global__ void __launch_bounds__(256, 3) k3_out(float* __restrict__ out) {
    int g = blockIdx.x * 256 + threadIdx.x;
    if (g >= NTHREAD_MAIN) return;
    const int fb = g % FBLK; int r1 = g / FBLK;
    const int t = r1 % T, b = r1 / T;
    const int f0 = fb * 4;

    ULL an[4][4];
#pragma unroll
    for (int p = 0; p < 4; ++p) {
        ULL bn = c_wpk[L_BN + p];
#pragma unroll
        for (int j = 0; j < 4; ++j) an[p][j] = bn;
    }

    int o = (b * C) * CH + t * FP + f0;
    // prologue: xp pair for ci=0 (g_xp has +CH slack for the last prefetch)
    float4 xa0 = ld4(g_xp + o),      xa1 = ld4(g_xp + o + 4);
    float4 xb0 = ld4(g_xp + o + FP), xb1 = ld4(g_xp + o + FP + 4);

    int wo = 0;
#pragma unroll 2
    for (int ci = 0; ci < C; ++ci) {
        float4 cxa0 = xa0, cxa1 = xa1, cxb0 = xb0, cxb1 = xb1;
        // rh loads for current iteration (inline, batched)
        const float* rhr = g_rh + o;
        float4 ra0 = ld4(rhr),      ra1 = ld4(rhr + 4);
        float4 rb0 = ld4(rhr + FP), rb1 = ld4(rhr + FP + 4);
        // prefetch next iteration's xp pair
        o += CH;
        xa0 = ld4(g_xp + o);      xa1 = ld4(g_xp + o + 4);
        xb0 = ld4(g_xp + o + FP); xb1 = ld4(g_xp + o + FP + 4);
        // compute
        conv_rowv(cxa0, cxa1, L_XN + wo,      an);
        conv_rowv(cxb0, cxb1, L_XN + wo + 20, an);
        conv_rowv(ra0,  ra1,  L_HN + wo,      an);
        conv_rowv(rb0,  rb1,  L_HN + wo + 20, an);
        wo += 40;
    }

#pragma unroll
    for (int p = 0; p < 4; ++p) {
        float nv[2][4];
#pragma unroll
        for (int j = 0; j < 4; ++j) {
            float a, bb;
            upk(an[p][j], a, bb);
            nv[0][j] = tanh_fast(a); nv[1][j] = tanh_fast(bb);
        }
#pragma unroll
        for (int half = 0; half < 2; ++half) {
            const int co = 2 * p + half;
            const int ro = (b * C + co) * CH + (t + 1) * FP + 2 + f0;
            const float* zrow = g_z + ro;
            const float* hrow = g_hpad + ro;
            float* orow = out + (b * C + co) * (T * F) + t * F + f0;
            float2 z01 = *reinterpret_cast<const float2*>(zrow);
            float2 z23 = *reinterpret_cast<const float2*>(zrow + 2);
            float2 h01 = *reinterpret_cast<const float2*>(hrow);
            float2 h23 = *reinterpret_cast<const float2*>(hrow + 2);
            float zz[4] = {z01.x, z01.y, z23.x, z23.y};
            float hh[4] = {h01.x, h01.y, h23.x, h23.y};
#pragma unroll
            for (int j = 0; j < 4; ++j) {
                if (f0 + j < F)
                    orow[j] = (1.0f - zz[j]) * hh[j] + zz[j] * nv[half][j];
            }
        }
    }
}

// ---------------------------------------------------------------------------
extern "C" void kernel_launch(void* const* d_in, const int* in_sizes, int n_in,
                              void* d_out, int out_size)
{
    (void)in_sizes; (void)n_in; (void)out_size;
    const float* x = (const float*)d_in[0];
    const float* h = (const float*)d_in[1];

    prep_pack<<<(WPK_N + 255) / 256, 256>>>(
        (const float*)d_in[2],  (const float*)d_in[3],
        (const float*)d_in[4],  (const float*)d_in[5],
        (const float*)d_in[6],  (const float*)d_in[7],
        (const float*)d_in[8],  (const float*)d_in[9],
        (const float*)d_in[10], (const float*)d_in[11],
        (const float*)d_in[12], (const float*)d_in[13],
        (const float*)d_in[14], (const float*)d_in[15]);

    // packed weights -> constant bank (graph-capturable D2D memcpy)
    void* wsrc = nullptr;
    cudaGetSymbolAddress(&wsrc, g_wpk);
    cudaMemcpyToSymbolAsync(c_wpk, wsrc, WPK_N * sizeof(ULL), 0,
                            cudaMemcpyDeviceToDevice, 0);

    {
        int tot = PAD_QX + PAD_QH;
        pad_all<<<(tot + 255) / 256, 256>>>(x, h);
    }
    const int gmain = (NTHREAD_MAIN + 255) / 256;
    k1_pre<<<gmain, 256>>>();
    k2_zr <<<gmain, 256>>>();
    k3_out<<<gmain, 256>>>((float*)d_out);
}

// round 16
// speedup vs baseline: 1.0066x; 1.0066x over previous
#include <cuda_runtime.h>
#include <math.h>

// ---------------------------------------------------------------------------
// MiniStageGRU on GB300 (sm_103a). Conv-GRU, convs (2,5), pad H(1,0) W(2,2).
// B=16, Cin_x=4, C=8, T=1000, F=257.
//
// Round-16 = round-14 (592.6us config: FP=272, 8co x 4f co-paired f32x2 tile,
// __constant__ weights via LDCU; k2 fully pipelined (256,2); k1/k3 (256,4);
// float4 pads) + stream-forked pad_h:
//   main stream: prep -> pad_x -> k1 ----------------+-> k2 -> k3
//   side stream:              \-> pad_h (parallel) --+
// pad_h is only needed by k2; graph capture records the fork as a DAG branch,
// so pad_h's HBM work overlaps k1's FMA work (the R10/11 block-interleaving
// attempt failed because the work distributor serializes phases of one grid;
// a DAG branch does not).
// Round-15's k3 partial pipeline reverted (neutral-negative).
// ---------------------------------------------------------------------------

typedef unsigned long long ULL;

static __device__ __forceinline__ ULL pk(float lo, float hi) {
    ULL r;
    asm("mov.b64 %0, {%1,%2};" : "=l"(r) : "f"(lo), "f"(hi));
    return r;
}
static __device__ __forceinline__ void upk(ULL v, float& lo, float& hi) {
    asm("mov.b64 {%0,%1}, %2;" : "=f"(lo), "=f"(hi) : "l"(v));
}
static __device__ __forceinline__ ULL ffma2(ULL a, ULL b, ULL c) {
    ULL d;
    asm("fma.rn.f32x2 %0, %1, %2, %3;" : "=l"(d) : "l"(a), "l"(b), "l"(c));
    return d;
}
static __device__ __forceinline__ float sigf(float x) {
    return __fdividef(1.0f, 1.0f + __expf(-x));
}
static __device__ __forceinline__ float tanh_fast(float x) {
    return __fdividef(2.0f, 1.0f + __expf(-2.0f * x)) - 1.0f;
}

constexpr int B    = 16;
constexpr int C    = 8;
constexpr int CIX  = 4;
constexpr int T    = 1000;
constexpr int TP1  = 1001;          // T+1 rows, row 0 = zeros
constexpr int F    = 257;
constexpr int FP   = 272;           // [2 left pad][257 data][13 right pad]
constexpr int CH   = TP1 * FP;
constexpr int FBLK = 65;

constexpr int NTHREAD_MAIN = B * T * FBLK;

// ---- packed-weight layout (ULL units) ---------------------------------------
constexpr int R1      = 0;          // K1: pre weights + bias
constexpr int L1_B    = 160;
constexpr int R1_N    = 164;
constexpr int R2      = R1_N;       // K2: xz, xr, hz, hr + biases
constexpr int L_XZ    = R2 + 0;
constexpr int L_XR    = R2 + 320;
constexpr int L_HZ    = R2 + 640;
constexpr int L_HR    = R2 + 960;
constexpr int L_BZ    = R2 + 1280;
constexpr int L_BR    = R2 + 1284;
constexpr int R2_N    = 1288;
constexpr int R3      = R2 + R2_N;  // K3: xn, hn + bias
constexpr int L_XN    = R3 + 0;
constexpr int L_HN    = R3 + 320;
constexpr int L_BN    = R3 + 640;
constexpr int R3_N    = 644;
constexpr int WPK_N   = R3 + R3_N;  // 2096

// ---- device scratch (+CH slack on arrays k2 prefetches) ----------------------
__device__ __align__(16) ULL   g_wpk[WPK_N];
__constant__ __align__(16) ULL c_wpk[WPK_N];
__device__ __align__(16) float g_xpad[(size_t)B * CIX * CH];
__device__ __align__(16) float g_hpad[(size_t)B * C   * CH + CH];
__device__ __align__(16) float g_xp  [(size_t)B * C   * CH + CH];
__device__ __align__(16) float g_z   [(size_t)B * C   * CH];
__device__ __align__(16) float g_rh  [(size_t)B * C   * CH];

// ---- weight packing: f32x2 co-pairs {w[2p], w[2p+1]} --------------------------
__global__ void prep_pack(const float* __restrict__ pre_w, const float* __restrict__ pre_b,
                          const float* __restrict__ xz_w,  const float* __restrict__ xz_b,
                          const float* __restrict__ xr_w,  const float* __restrict__ xr_b,
                          const float* __restrict__ xn_w,  const float* __restrict__ xn_b,
                          const float* __restrict__ hz_w,  const float* __restrict__ hz_b,
                          const float* __restrict__ hr_w,  const float* __restrict__ hr_b,
                          const float* __restrict__ hn_w,  const float* __restrict__ hn_b)
{
    int i = blockIdx.x * blockDim.x + threadIdx.x;
    if (i >= WPK_N) return;
    ULL v;
    if (i < L1_B) {                                    // pre weights (CIN=4)
        int r = i; int p = r & 3; int s = r >> 2;
        int kw = s % 5; s /= 5; int kh = s & 1; int ci = s >> 1;
        v = pk(pre_w[((2 * p)     * CIX + ci) * 10 + kh * 5 + kw],
               pre_w[((2 * p + 1) * CIX + ci) * 10 + kh * 5 + kw]);
    } else if (i < R1_N) {
        int p = i - L1_B;
        v = pk(pre_b[2 * p], pre_b[2 * p + 1]);
    } else if (i < L_BZ) {                             // xz/xr/hz/hr weights
        int j = i - R2;
        int gi = j / 320, r = j % 320;
        int p = r & 3; int s = r >> 2;
        int kw = s % 5; s /= 5; int kh = s & 1; int ci = s >> 1;
        const float* w = (gi == 0) ? xz_w : (gi == 1) ? xr_w : (gi == 2) ? hz_w : hr_w;
        v = pk(w[((2 * p)     * C + ci) * 10 + kh * 5 + kw],
               w[((2 * p + 1) * C + ci) * 10 + kh * 5 + kw]);
    } else if (i < L_BR) {
        int p = i - L_BZ;
        v = pk(xz_b[2 * p] + hz_b[2 * p], xz_b[2 * p + 1] + hz_b[2 * p + 1]);
    } else if (i < R3) {
        int p = i - L_BR;
        v = pk(xr_b[2 * p] + hr_b[2 * p], xr_b[2 * p + 1] + hr_b[2 * p + 1]);
    } else if (i < L_BN) {                             // xn/hn weights
        int j = i - R3;
        int gi = j / 320, r = j % 320;
        int p = r & 3; int s = r >> 2;
        int kw = s % 5; s /= 5; int kh = s & 1; int ci = s >> 1;
        const float* w = gi ? hn_w : xn_w;
        v = pk(w[((2 * p)     * C + ci) * 10 + kh * 5 + kw],
               w[((2 * p + 1) * C + ci) * 10 + kh * 5 + kw]);
    } else {
        int p = i - L_BN;
        v = pk(xn_b[2 * p] + hn_b[2 * p], xn_b[2 * p + 1] + hn_b[2 * p + 1]);
    }
    g_wpk[i] = v;
}

// ---- conv row micro-kernels: window by VALUE, weights from __constant__ ------
static __device__ __forceinline__ void conv_rowv(
    float4 A, float4 Bv, int woff, ULL acc[4][4])
{
    float win[8] = {A.x, A.y, A.z, A.w, Bv.x, Bv.y, Bv.z, Bv.w};
    ULL wb[8];
#pragma unroll
    for (int m = 0; m < 8; ++m) wb[m] = pk(win[m], win[m]);
#pragma unroll
    for (int kw = 0; kw < 5; ++kw) {
        ULL w0 = c_wpk[woff + kw * 4 + 0];
        ULL w1 = c_wpk[woff + kw * 4 + 1];
        ULL w2 = c_wpk[woff + kw * 4 + 2];
        ULL w3 = c_wpk[woff + kw * 4 + 3];
#pragma unroll
        for (int j = 0; j < 4; ++j) {
            acc[0][j] = ffma2(w0, wb[j + kw], acc[0][j]);
            acc[1][j] = ffma2(w1, wb[j + kw], acc[1][j]);
            acc[2][j] = ffma2(w2, wb[j + kw], acc[2][j]);
            acc[3][j] = ffma2(w3, wb[j + kw], acc[3][j]);
        }
    }
}

static __device__ __forceinline__ void conv_row_dualv(
    float4 A, float4 Bv, int woff1, int woff2,
    ULL a1[4][4], ULL a2[4][4])
{
    float win[8] = {A.x, A.y, A.z, A.w, Bv.x, Bv.y, Bv.z, Bv.w};
    ULL wb[8];
#pragma unroll
    for (int m = 0; m < 8; ++m) wb[m] = pk(win[m], win[m]);
#pragma unroll
    for (int kw = 0; kw < 5; ++kw) {
        ULL u0 = c_wpk[woff1 + kw * 4 + 0];
        ULL u1 = c_wpk[woff1 + kw * 4 + 1];
        ULL u2 = c_wpk[woff1 + kw * 4 + 2];
        ULL u3 = c_wpk[woff1 + kw * 4 + 3];
        ULL v0 = c_wpk[woff2 + kw * 4 + 0];
        ULL v1 = c_wpk[woff2 + kw * 4 + 1];
        ULL v2 = c_wpk[woff2 + kw * 4 + 2];
        ULL v3 = c_wpk[woff2 + kw * 4 + 3];
#pragma unroll
        for (int j = 0; j < 4; ++j) {
            a1[0][j] = ffma2(u0, wb[j + kw], a1[0][j]);
            a1[1][j] = ffma2(u1, wb[j + kw], a1[1][j]);
            a1[2][j] = ffma2(u2, wb[j + kw], a1[2][j]);
            a1[3][j] = ffma2(u3, wb[j + kw], a1[3][j]);
            a2[0][j] = ffma2(v0, wb[j + kw], a2[0][j]);
            a2[1][j] = ffma2(v1, wb[j + kw], a2[1][j]);
            a2[2][j] = ffma2(v2, wb[j + kw], a2[2][j]);
            a2[3][j] = ffma2(v3, wb[j + kw], a2[3][j]);
        }
    }
}

static __device__ __forceinline__ float4 ld4(const float* p) {
    return *reinterpret_cast<const float4*>(p);
}
static __device__ __forceinline__ void st2(float* p, float a, float b) {
    *reinterpret_cast<float2*>(p) = make_float2(a, b);
}

// ---- pad kernels (float4 quads) -----------------------------------------------
constexpr int PAD_QX = B * CIX * CH / 4;
constexpr int PAD_QH = B * C * CH / 4;

__global__ void pad_x_k(const float* __restrict__ x) {
    int g = blockIdx.x * blockDim.x + threadIdx.x;
    if (g >= PAD_QX) return;
    int e0 = g * 4;
    int fm = e0 % FP;
    int r  = e0 / FP;
    int tr = r % TP1;
    int bc = r / TP1;
    float4 v = make_float4(0.f, 0.f, 0.f, 0.f);
    if (tr > 0) {
        const float* srow = x + (bc * T + tr - 1) * F;
        int f0 = fm - 2;
        if (f0 >= 0 && f0 < F)         v.x = srow[f0];
        if (f0 + 1 >= 0 && f0 + 1 < F) v.y = srow[f0 + 1];
        if (f0 + 2 >= 0 && f0 + 2 < F) v.z = srow[f0 + 2];
        if (f0 + 3 >= 0 && f0 + 3 < F) v.w = srow[f0 + 3];
    }
    *reinterpret_cast<float4*>(g_xpad + e0) = v;
}

__global__ void pad_h_k(const float* __restrict__ h) {
    int g = blockIdx.x * blockDim.x + threadIdx.x;
    if (g >= PAD_QH) return;
    int e0 = g * 4;
    int fm = e0 % FP;
    int r  = e0 / FP;
    int tr = r % TP1;
    int bc = r / TP1;
    float4 v = make_float4(0.f, 0.f, 0.f, 0.f);
    if (tr > 0) {
        const float* srow = h + (bc * T + tr - 1) * F;
        int f0 = fm - 2;
        if (f0 >= 0 && f0 < F)         v.x = srow[f0];
        if (f0 + 1 >= 0 && f0 + 1 < F) v.y = srow[f0 + 1];
        if (f0 + 2 >= 0 && f0 + 2 < F) v.z = srow[f0 + 2];
        if (f0 + 3 >= 0 && f0 + 3 < F) v.w = srow[f0 + 3];
    } else {
        // zero row 0 of intermediates (read by k2/k3 at t=0).
        // g_xp row 0 is not touched by k1 (k1 writes rows 1..T), so writing it
        // here, concurrent with k1, is race-free.
        *reinterpret_cast<float4*>(g_xp + e0) = v;
        *reinterpret_cast<float4*>(g_rh + e0) = v;
    }
    *reinterpret_cast<float4*>(g_hpad + e0) = v;
}

// ---- K1: xp = elu(conv(x, pre)) -----------------------------------------------
__global__ void __launch_bounds__(256, 4) k1_pre() {
    int g = blockIdx.x * 256 + threadIdx.x;
    if (g >= NTHREAD_MAIN) return;
    const int fb = g % FBLK; int r1 = g / FBLK;
    const int t = r1 % T, b = r1 / T;
    const int f0 = fb * 4;

    ULL acc[4][4];
#pragma unroll
    for (int p = 0; p < 4; ++p) {
        ULL bb = c_wpk[L1_B + p];
#pragma unroll
        for (int j = 0; j < 4; ++j) acc[p][j] = bb;
    }

    int o = (b * CIX) * CH + t * FP + f0;
#pragma unroll
    for (int ci = 0; ci < CIX; ++ci) {
        const float* r0 = g_xpad + o;
        float4 a0 = ld4(r0),      a1 = ld4(r0 + 4);
        float4 b0 = ld4(r0 + FP), b1 = ld4(r0 + FP + 4);
        conv_rowv(a0, a1, R1 + ci * 40,      acc);
        conv_rowv(b0, b1, R1 + ci * 40 + 20, acc);
        o += CH;
    }

    const bool lastfb = (fb == FBLK - 1);
#pragma unroll
    for (int p = 0; p < 4; ++p) {
        float* rowA = g_xp + (b * C + 2 * p)     * CH + (t + 1) * FP + 2 + f0;
        float* rowB = g_xp + (b * C + 2 * p + 1) * CH + (t + 1) * FP + 2 + f0;
        float v[2][4];
#pragma unroll
        for (int j = 0; j < 4; ++j) {
            float lo, hi;
            upk(acc[p][j], lo, hi);
            lo = lo > 0.0f ? lo : (__expf(lo) - 1.0f);
            hi = hi > 0.0f ? hi : (__expf(hi) - 1.0f);
            bool valid = (f0 + j) < F;
            v[0][j] = valid ? lo : 0.0f;
            v[1][j] = valid ? hi : 0.0f;
        }
        st2(rowA,     v[0][0], v[0][1]); st2(rowA + 2, v[0][2], v[0][3]);
        st2(rowB,     v[1][0], v[1][1]); st2(rowB + 2, v[1][2], v[1][3]);
        if (fb == 0) { st2(rowA - 2, 0.f, 0.f); st2(rowB - 2, 0.f, 0.f); }
        if (lastfb) {
#pragma unroll
            for (int q = 4; q < 14; q += 2) { st2(rowA + q, 0.f, 0.f); st2(rowB + q, 0.f, 0.f); }
        }
    }
}

// ---- K2: z and r*h (fully software-pipelined ci loop) --------------------------
__global__ void __launch_bounds__(256, 2) k2_zr() {
    int g = blockIdx.x * 256 + threadIdx.x;
    if (g >= NTHREAD_MAIN) return;
    const int fb = g % FBLK; int r1 = g / FBLK;
    const int t = r1 % T, b = r1 / T;
    const int f0 = fb * 4;

    ULL az[4][4], ar[4][4];
#pragma unroll
    for (int p = 0; p < 4; ++p) {
        ULL bz = c_wpk[L_BZ + p], br = c_wpk[L_BR + p];
#pragma unroll
        for (int j = 0; j < 4; ++j) { az[p][j] = bz; ar[p][j] = br; }
    }

    int o = (b * C) * CH + t * FP + f0;
    float4 xa0 = ld4(g_xp + o),        xa1 = ld4(g_xp + o + 4);
    float4 xb0 = ld4(g_xp + o + FP),   xb1 = ld4(g_xp + o + FP + 4);
    float4 ha0 = ld4(g_hpad + o),      ha1 = ld4(g_hpad + o + 4);
    float4 hb0 = ld4(g_hpad + o + FP), hb1 = ld4(g_hpad + o + FP + 4);

    int wo = 0;
#pragma unroll 2
    for (int ci = 0; ci < C; ++ci) {
        float4 cxa0 = xa0, cxa1 = xa1, cxb0 = xb0, cxb1 = xb1;
        float4 cha0 = ha0, cha1 = ha1, chb0 = hb0, chb1 = hb1;
        o += CH;
        xa0 = ld4(g_xp + o);        xa1 = ld4(g_xp + o + 4);
        xb0 = ld4(g_xp + o + FP);   xb1 = ld4(g_xp + o + FP + 4);
        ha0 = ld4(g_hpad + o);      ha1 = ld4(g_hpad + o + 4);
        hb0 = ld4(g_hpad + o + FP); hb1 = ld4(g_hpad + o + FP + 4);
        conv_row_dualv(cxa0, cxa1, L_XZ + wo,      L_XR + wo,      az, ar);
        conv_row_dualv(cxb0, cxb1, L_XZ + wo + 20, L_XR + wo + 20, az, ar);
        conv_row_dualv(cha0, cha1, L_HZ + wo,      L_HR + wo,      az, ar);
        conv_row_dualv(chb0, chb1, L_HZ + wo + 20, L_HR + wo + 20, az, ar);
        wo += 40;
    }

    const bool lastfb = (fb == FBLK - 1);
#pragma unroll
    for (int p = 0; p < 4; ++p) {
        float zv[2][4], rv[2][4];
#pragma unroll
        for (int j = 0; j < 4; ++j) {
            float a, bb;
            upk(az[p][j], a, bb); zv[0][j] = sigf(a); zv[1][j] = sigf(bb);
            upk(ar[p][j], a, bb); rv[0][j] = sigf(a); rv[1][j] = sigf(bb);
        }
#pragma unroll
        for (int half = 0; half < 2; ++half) {
            const int co = 2 * p + half;
            const int ro = (b * C + co) * CH + (t + 1) * FP + 2 + f0;
            const float* hrow = g_hpad + ro;
            float* zrow  = g_z  + ro;
            float* rhrow = g_rh + ro;
            float2 h01 = *reinterpret_cast<const float2*>(hrow);
            float2 h23 = *reinterpret_cast<const float2*>(hrow + 2);
            st2(zrow,      zv[half][0], zv[half][1]);
            st2(zrow + 2,  zv[half][2], zv[half][3]);
            st2(rhrow,     rv[half][0] * h01.x, rv[half][1] * h01.y);
            st2(rhrow + 2, rv[half][2] * h23.x, rv[half][3] * h23.y);
            if (fb == 0) st2(rhrow - 2, 0.f, 0.f);
            if (lastfb) {
#pragma unroll
                for (int q = 4; q < 14; q += 2) st2(rhrow + q, 0.f, 0.f);
            }
        }
    }
}

// ---- K3: n + output (round-14 non-pipelined form) -------------------------------
__global__ void __launch_bounds__(256, 4) k3_out(float* __restrict__ out) {
    int g = blockIdx.x * 256 + threadIdx.x;
    if (g >= NTHREAD_MAIN) return;
    const int fb = g % FBLK; int r1 = g / FBLK;
    const int t = r1 % T, b = r1 / T;
    const int f0 = fb * 4;

    ULL an[4][4];
#pragma unroll
    for (int p = 0; p < 4; ++p) {
        ULL bn = c_wpk[L_BN + p];
#pragma unroll
        for (int j = 0; j < 4; ++j) an[p][j] = bn;
    }

    int o = (b * C) * CH + t * FP + f0;
    int wo = 0;
#pragma unroll 2
    for (int ci = 0; ci < C; ++ci) {
        const float* xr  = g_xp + o;
        const float* rhr = g_rh + o;
        float4 xa0 = ld4(xr),       xa1 = ld4(xr + 4);
        float4 xb0 = ld4(xr + FP),  xb1 = ld4(xr + FP + 4);
        float4 ra0 = ld4(rhr),      ra1 = ld4(rhr + 4);
        float4 rb0 = ld4(rhr + FP), rb1 = ld4(rhr + FP + 4);
        conv_rowv(xa0, xa1, L_XN + wo,      an);
        conv_rowv(xb0, xb1, L_XN + wo + 20, an);
        conv_rowv(ra0, ra1, L_HN + wo,      an);
        conv_rowv(rb0, rb1, L_HN + wo + 20, an);
        o += CH; wo += 40;
    }

#pragma unroll
    for (int p = 0; p < 4; ++p) {
        float nv[2][4];
#pragma unroll
        for (int j = 0; j < 4; ++j) {
            float a, bb;
            upk(an[p][j], a, bb);
            nv[0][j] = tanh_fast(a); nv[1][j] = tanh_fast(bb);
        }
#pragma unroll
        for (int half = 0; half < 2; ++half) {
            const int co = 2 * p + half;
            const int ro = (b * C + co) * CH + (t + 1) * FP + 2 + f0;
            const float* zrow = g_z + ro;
            const float* hrow = g_hpad + ro;
            float* orow = out + (b * C + co) * (T * F) + t * F + f0;
            float2 z01 = *reinterpret_cast<const float2*>(zrow);
            float2 z23 = *reinterpret_cast<const float2*>(zrow + 2);
            float2 h01 = *reinterpret_cast<const float2*>(hrow);
            float2 h23 = *reinterpret_cast<const float2*>(hrow + 2);
            float zz[4] = {z01.x, z01.y, z23.x, z23.y};
            float hh[4] = {h01.x, h01.y, h23.x, h23.y};
#pragma unroll
            for (int j = 0; j < 4; ++j) {
                if (f0 + j < F)
                    orow[j] = (1.0f - zz[j]) * hh[j] + zz[j] * nv[half][j];
            }
        }
    }
}

// ---------------------------------------------------------------------------
extern "C" void kernel_launch(void* const* d_in, const int* in_sizes, int n_in,
                              void* d_out, int out_size)
{
    (void)in_sizes; (void)n_in; (void)out_size;
    const float* x = (const float*)d_in[0];
    const float* h = (const float*)d_in[1];

    // Lazily created side stream + events (host-side resources only; no device
    // memory). Reused across calls -> identical captured graph every time.
    static cudaStream_t s2 = nullptr;
    static cudaEvent_t evFork = nullptr, evJoin = nullptr;
    if (!s2) {
        cudaStreamCreateWithFlags(&s2, cudaStreamNonBlocking);
        cudaEventCreateWithFlags(&evFork, cudaEventDisableTiming);
        cudaEventCreateWithFlags(&evJoin, cudaEventDisableTiming);
    }

    // main stream: weight packing + x padding
    prep_pack<<<(WPK_N + 255) / 256, 256>>>(
        (const float*)d_in[2],  (const float*)d_in[3],
        (const float*)d_in[4],  (const float*)d_in[5],
        (const float*)d_in[6],  (const float*)d_in[7],
        (const float*)d_in[8],  (const float*)d_in[9],
        (const float*)d_in[10], (const float*)d_in[11],
        (const float*)d_in[12], (const float*)d_in[13],
        (const float*)d_in[14], (const float*)d_in[15]);

    void* wsrc = nullptr;
    cudaGetSymbolAddress(&wsrc, g_wpk);
    cudaMemcpyToSymbolAsync(c_wpk, wsrc, WPK_N * sizeof(ULL), 0,
                            cudaMemcpyDeviceToDevice, 0);

    pad_x_k<<<(PAD_QX + 255) / 256, 256>>>(x);

    // fork: pad_h runs on side stream, overlapping k1 on the main stream
    cudaEventRecord(evFork, 0);
    cudaStreamWaitEvent(s2, evFork, 0);
    pad_h_k<<<(PAD_QH + 255) / 256, 256, 0, s2>>>(h);
    cudaEventRecord(evJoin, s2);

    const int gmain = (NTHREAD_MAIN + 255) / 256;
    k1_pre<<<gmain, 256>>>();

    // join: k2 needs both k1 (g_xp) and pad_h (g_hpad, zero rows)
    cudaStreamWaitEvent(0, evJoin, 0);
    k2_zr <<<gmain, 256>>>();
    k3_out<<<gmain, 256>>>((float*)d_out);
}

// round 17
// speedup vs baseline: 1.0105x; 1.0039x over previous
#include <cuda_runtime.h>
#include <math.h>

// ---------------------------------------------------------------------------
// MiniStageGRU on GB300 (sm_103a). Conv-GRU, convs (2,5), pad H(1,0) W(2,2).
// B=16, Cin_x=4, C=8, T=1000, F=257.
//
// Round-17 = round-16 (592.3us: FP=272, 8co x 4f co-paired f32x2 tile,
// __constant__ weights via LDCU; k2 fully register-pipelined (256,2);
// k1/k3 (256,4); float4 pads; stream-forked pad_h overlapping k1)
// + prefetch.global.L2 for next-iteration rows in k3 (4/iter) and k1 (2/iter).
// Zero register cost -> no occupancy price (the failure mode of R13/R15).
// ---------------------------------------------------------------------------

typedef unsigned long long ULL;

static __device__ __forceinline__ ULL pk(float lo, float hi) {
    ULL r;
    asm("mov.b64 %0, {%1,%2};" : "=l"(r) : "f"(lo), "f"(hi));
    return r;
}
static __device__ __forceinline__ void upk(ULL v, float& lo, float& hi) {
    asm("mov.b64 {%0,%1}, %2;" : "=f"(lo), "=f"(hi) : "l"(v));
}
static __device__ __forceinline__ ULL ffma2(ULL a, ULL b, ULL c) {
    ULL d;
    asm("fma.rn.f32x2 %0, %1, %2, %3;" : "=l"(d) : "l"(a), "l"(b), "l"(c));
    return d;
}
static __device__ __forceinline__ float sigf(float x) {
    return __fdividef(1.0f, 1.0f + __expf(-x));
}
static __device__ __forceinline__ float tanh_fast(float x) {
    return __fdividef(2.0f, 1.0f + __expf(-2.0f * x)) - 1.0f;
}
static __device__ __forceinline__ void pf_l2(const float* p) {
    asm volatile("prefetch.global.L2 [%0];" :: "l"(p));
}

constexpr int B    = 16;
constexpr int C    = 8;
constexpr int CIX  = 4;
constexpr int T    = 1000;
constexpr int TP1  = 1001;          // T+1 rows, row 0 = zeros
constexpr int F    = 257;
constexpr int FP   = 272;           // [2 left pad][257 data][13 right pad]
constexpr int CH   = TP1 * FP;
constexpr int FBLK = 65;

constexpr int NTHREAD_MAIN = B * T * FBLK;

// ---- packed-weight layout (ULL units) ---------------------------------------
constexpr int R1      = 0;          // K1: pre weights + bias
constexpr int L1_B    = 160;
constexpr int R1_N    = 164;
constexpr int R2      = R1_N;       // K2: xz, xr, hz, hr + biases
constexpr int L_XZ    = R2 + 0;
constexpr int L_XR    = R2 + 320;
constexpr int L_HZ    = R2 + 640;
constexpr int L_HR    = R2 + 960;
constexpr int L_BZ    = R2 + 1280;
constexpr int L_BR    = R2 + 1284;
constexpr int R2_N    = 1288;
constexpr int R3      = R2 + R2_N;  // K3: xn, hn + bias
constexpr int L_XN    = R3 + 0;
constexpr int L_HN    = R3 + 320;
constexpr int L_BN    = R3 + 640;
constexpr int R3_N    = 644;
constexpr int WPK_N   = R3 + R3_N;  // 2096

// ---- device scratch (+CH slack on arrays that get prefetched) ----------------
__device__ __align__(16) ULL   g_wpk[WPK_N];
__constant__ __align__(16) ULL c_wpk[WPK_N];
__device__ __align__(16) float g_xpad[(size_t)B * CIX * CH + CH];
__device__ __align__(16) float g_hpad[(size_t)B * C   * CH + CH];
__device__ __align__(16) float g_xp  [(size_t)B * C   * CH + CH];
__device__ __align__(16) float g_z   [(size_t)B * C   * CH];
__device__ __align__(16) float g_rh  [(size_t)B * C   * CH + CH];

// ---- weight packing: f32x2 co-pairs {w[2p], w[2p+1]} --------------------------
__global__ void prep_pack(const float* __restrict__ pre_w, const float* __restrict__ pre_b,
                          const float* __restrict__ xz_w,  const float* __restrict__ xz_b,
                          const float* __restrict__ xr_w,  const float* __restrict__ xr_b,
                          const float* __restrict__ xn_w,  const float* __restrict__ xn_b,
                          const float* __restrict__ hz_w,  const float* __restrict__ hz_b,
                          const float* __restrict__ hr_w,  const float* __restrict__ hr_b,
                          const float* __restrict__ hn_w,  const float* __restrict__ hn_b)
{
    int i = blockIdx.x * blockDim.x + threadIdx.x;
    if (i >= WPK_N) return;
    ULL v;
    if (i < L1_B) {                                    // pre weights (CIN=4)
        int r = i; int p = r & 3; int s = r >> 2;
        int kw = s % 5; s /= 5; int kh = s & 1; int ci = s >> 1;
        v = pk(pre_w[((2 * p)     * CIX + ci) * 10 + kh * 5 + kw],
               pre_w[((2 * p + 1) * CIX + ci) * 10 + kh * 5 + kw]);
    } else if (i < R1_N) {
        int p = i - L1_B;
        v = pk(pre_b[2 * p], pre_b[2 * p + 1]);
    } else if (i < L_BZ) {                             // xz/xr/hz/hr weights
        int j = i - R2;
        int gi = j / 320, r = j % 320;
        int p = r & 3; int s = r >> 2;
        int kw = s % 5; s /= 5; int kh = s & 1; int ci = s >> 1;
        const float* w = (gi == 0) ? xz_w : (gi == 1) ? xr_w : (gi == 2) ? hz_w : hr_w;
        v = pk(w[((2 * p)     * C + ci) * 10 + kh * 5 + kw],
               w[((2 * p + 1) * C + ci) * 10 + kh * 5 + kw]);
    } else if (i < L_BR) {
        int p = i - L_BZ;
        v = pk(xz_b[2 * p] + hz_b[2 * p], xz_b[2 * p + 1] + hz_b[2 * p + 1]);
    } else if (i < R3) {
        int p = i - L_BR;
        v = pk(xr_b[2 * p] + hr_b[2 * p], xr_b[2 * p + 1] + hr_b[2 * p + 1]);
    } else if (i < L_BN) {                             // xn/hn weights
        int j = i - R3;
        int gi = j / 320, r = j % 320;
        int p = r & 3; int s = r >> 2;
        int kw = s % 5; s /= 5; int kh = s & 1; int ci = s >> 1;
        const float* w = gi ? hn_w : xn_w;
        v = pk(w[((2 * p)     * C + ci) * 10 + kh * 5 + kw],
               w[((2 * p + 1) * C + ci) * 10 + kh * 5 + kw]);
    } else {
        int p = i - L_BN;
        v = pk(xn_b[2 * p] + hn_b[2 * p], xn_b[2 * p + 1] + hn_b[2 * p + 1]);
    }
    g_wpk[i] = v;
}

// ---- conv row micro-kernels: window by VALUE, weights from __constant__ ------
static __device__ __forceinline__ void conv_rowv(
    float4 A, float4 Bv, int woff, ULL acc[4][4])
{
    float win[8] = {A.x, A.y, A.z, A.w, Bv.x, Bv.y, Bv.z, Bv.w};
    ULL wb[8];
#pragma unroll
    for (int m = 0; m < 8; ++m) wb[m] = pk(win[m], win[m]);
#pragma unroll
    for (int kw = 0; kw < 5; ++kw) {
        ULL w0 = c_wpk[woff + kw * 4 + 0];
        ULL w1 = c_wpk[woff + kw * 4 + 1];
        ULL w2 = c_wpk[woff + kw * 4 + 2];
        ULL w3 = c_wpk[woff + kw * 4 + 3];
#pragma unroll
        for (int j = 0; j < 4; ++j) {
            acc[0][j] = ffma2(w0, wb[j + kw], acc[0][j]);
            acc[1][j] = ffma2(w1, wb[j + kw], acc[1][j]);
            acc[2][j] = ffma2(w2, wb[j + kw], acc[2][j]);
            acc[3][j] = ffma2(w3, wb[j + kw], acc[3][j]);
        }
    }
}

static __device__ __forceinline__ void conv_row_dualv(
    float4 A, float4 Bv, int woff1, int woff2,
    ULL a1[4][4], ULL a2[4][4])
{
    float win[8] = {A.x, A.y, A.z, A.w, Bv.x, Bv.y, Bv.z, Bv.w};
    ULL wb[8];
#pragma unroll
    for (int m = 0; m < 8; ++m) wb[m] = pk(win[m], win[m]);
#pragma unroll
    for (int kw = 0; kw < 5; ++kw) {
        ULL u0 = c_wpk[woff1 + kw * 4 + 0];
        ULL u1 = c_wpk[woff1 + kw * 4 + 1];
        ULL u2 = c_wpk[woff1 + kw * 4 + 2];
        ULL u3 = c_wpk[woff1 + kw * 4 + 3];
        ULL v0 = c_wpk[woff2 + kw * 4 + 0];
        ULL v1 = c_wpk[woff2 + kw * 4 + 1];
        ULL v2 = c_wpk[woff2 + kw * 4 + 2];
        ULL v3 = c_wpk[woff2 + kw * 4 + 3];
#pragma unroll
        for (int j = 0; j < 4; ++j) {
            a1[0][j] = ffma2(u0, wb[j + kw], a1[0][j]);
            a1[1][j] = ffma2(u1, wb[j + kw], a1[1][j]);
            a1[2][j] = ffma2(u2, wb[j + kw], a1[2][j]);
            a1[3][j] = ffma2(u3, wb[j + kw], a1[3][j]);
            a2[0][j] = ffma2(v0, wb[j + kw], a2[0][j]);
            a2[1][j] = ffma2(v1, wb[j + kw], a2[1][j]);
            a2[2][j] = ffma2(v2, wb[j + kw], a2[2][j]);
            a2[3][j] = ffma2(v3, wb[j + kw], a2[3][j]);
        }
    }
}

static __device__ __forceinline__ float4 ld4(const float* p) {
    return *reinterpret_cast<const float4*>(p);
}
static __device__ __forceinline__ void st2(float* p, float a, float b) {
    *reinterpret_cast<float2*>(p) = make_float2(a, b);
}

// ---- pad kernels (float4 quads) -----------------------------------------------
constexpr int PAD_QX = B * CIX * CH / 4;
constexpr int PAD_QH = B * C * CH / 4;

__global__ void pad_x_k(const float* __restrict__ x) {
    int g = blockIdx.x * blockDim.x + threadIdx.x;
    if (g >= PAD_QX) return;
    int e0 = g * 4;
    int fm = e0 % FP;
    int r  = e0 / FP;
    int tr = r % TP1;
    int bc = r / TP1;
    float4 v = make_float4(0.f, 0.f, 0.f, 0.f);
    if (tr > 0) {
        const float* srow = x + (bc * T + tr - 1) * F;
        int f0 = fm - 2;
        if (f0 >= 0 && f0 < F)         v.x = srow[f0];
        if (f0 + 1 >= 0 && f0 + 1 < F) v.y = srow[f0 + 1];
        if (f0 + 2 >= 0 && f0 + 2 < F) v.z = srow[f0 + 2];
        if (f0 + 3 >= 0 && f0 + 3 < F) v.w = srow[f0 + 3];
    }
    *reinterpret_cast<float4*>(g_xpad + e0) = v;
}

__global__ void pad_h_k(const float* __restrict__ h) {
    int g = blockIdx.x * blockDim.x + threadIdx.x;
    if (g >= PAD_QH) return;
    int e0 = g * 4;
    int fm = e0 % FP;
    int r  = e0 / FP;
    int tr = r % TP1;
    int bc = r / TP1;
    float4 v = make_float4(0.f, 0.f, 0.f, 0.f);
    if (tr > 0) {
        const float* srow = h + (bc * T + tr - 1) * F;
        int f0 = fm - 2;
        if (f0 >= 0 && f0 < F)         v.x = srow[f0];
        if (f0 + 1 >= 0 && f0 + 1 < F) v.y = srow[f0 + 1];
        if (f0 + 2 >= 0 && f0 + 2 < F) v.z = srow[f0 + 2];
        if (f0 + 3 >= 0 && f0 + 3 < F) v.w = srow[f0 + 3];
    } else {
        // zero row 0 of intermediates (k1 writes rows 1..T only -> race-free)
        *reinterpret_cast<float4*>(g_xp + e0) = v;
        *reinterpret_cast<float4*>(g_rh + e0) = v;
    }
    *reinterpret_cast<float4*>(g_hpad + e0) = v;
}

// ---- K1: xp = elu(conv(x, pre))  (+L2 prefetch) ---------------------------------
__global__ void __launch_bounds__(256, 4) k1_pre() {
    int g = blockIdx.x * 256 + threadIdx.x;
    if (g >= NTHREAD_MAIN) return;
    const int fb = g % FBLK; int r1 = g / FBLK;
    const int t = r1 % T, b = r1 / T;
    const int f0 = fb * 4;

    ULL acc[4][4];
#pragma unroll
    for (int p = 0; p < 4; ++p) {
        ULL bb = c_wpk[L1_B + p];
#pragma unroll
        for (int j = 0; j < 4; ++j) acc[p][j] = bb;
    }

    int o = (b * CIX) * CH + t * FP + f0;
#pragma unroll
    for (int ci = 0; ci < CIX; ++ci) {
        const float* r0 = g_xpad + o;
        // L2 prefetch of next iteration's rows (zero register cost; +CH slack)
        pf_l2(r0 + CH);
        pf_l2(r0 + CH + FP);
        float4 a0 = ld4(r0),      a1 = ld4(r0 + 4);
        float4 b0 = ld4(r0 + FP), b1 = ld4(r0 + FP + 4);
        conv_rowv(a0, a1, R1 + ci * 40,      acc);
        conv_rowv(b0, b1, R1 + ci * 40 + 20, acc);
        o += CH;
    }

    const bool lastfb = (fb == FBLK - 1);
#pragma unroll
    for (int p = 0; p < 4; ++p) {
        float* rowA = g_xp + (b * C + 2 * p)     * CH + (t + 1) * FP + 2 + f0;
        float* rowB = g_xp + (b * C + 2 * p + 1) * CH + (t + 1) * FP + 2 + f0;
        float v[2][4];
#pragma unroll
        for (int j = 0; j < 4; ++j) {
            float lo, hi;
            upk(acc[p][j], lo, hi);
            lo = lo > 0.0f ? lo : (__expf(lo) - 1.0f);
            hi = hi > 0.0f ? hi : (__expf(hi) - 1.0f);
            bool valid = (f0 + j) < F;
            v[0][j] = valid ? lo : 0.0f;
            v[1][j] = valid ? hi : 0.0f;
        }
        st2(rowA,     v[0][0], v[0][1]); st2(rowA + 2, v[0][2], v[0][3]);
        st2(rowB,     v[1][0], v[1][1]); st2(rowB + 2, v[1][2], v[1][3]);
        if (fb == 0) { st2(rowA - 2, 0.f, 0.f); st2(rowB - 2, 0.f, 0.f); }
        if (lastfb) {
#pragma unroll
            for (int q = 4; q < 14; q += 2) { st2(rowA + q, 0.f, 0.f); st2(rowB + q, 0.f, 0.f); }
        }
    }
}

// ---- K2: z and r*h (fully register-pipelined ci loop) --------------------------
__global__ void __launch_bounds__(256, 2) k2_zr() {
    int g = blockIdx.x * 256 + threadIdx.x;
    if (g >= NTHREAD_MAIN) return;
    const int fb = g % FBLK; int r1 = g / FBLK;
    const int t = r1 % T, b = r1 / T;
    const int f0 = fb * 4;

    ULL az[4][4], ar[4][4];
#pragma unroll
    for (int p = 0; p < 4; ++p) {
        ULL bz = c_wpk[L_BZ + p], br = c_wpk[L_BR + p];
#pragma unroll
        for (int j = 0; j < 4; ++j) { az[p][j] = bz; ar[p][j] = br; }
    }

    int o = (b * C) * CH + t * FP + f0;
    float4 xa0 = ld4(g_xp + o),        xa1 = ld4(g_xp + o + 4);
    float4 xb0 = ld4(g_xp + o + FP),   xb1 = ld4(g_xp + o + FP + 4);
    float4 ha0 = ld4(g_hpad + o),      ha1 = ld4(g_hpad + o + 4);
    float4 hb0 = ld4(g_hpad + o + FP), hb1 = ld4(g_hpad + o + FP + 4);

    int wo = 0;
#pragma unroll 2
    for (int ci = 0; ci < C; ++ci) {
        float4 cxa0 = xa0, cxa1 = xa1, cxb0 = xb0, cxb1 = xb1;
        float4 cha0 = ha0, cha1 = ha1, chb0 = hb0, chb1 = hb1;
        o += CH;
        xa0 = ld4(g_xp + o);        xa1 = ld4(g_xp + o + 4);
        xb0 = ld4(g_xp + o + FP);   xb1 = ld4(g_xp + o + FP + 4);
        ha0 = ld4(g_hpad + o);      ha1 = ld4(g_hpad + o + 4);
        hb0 = ld4(g_hpad + o + FP); hb1 = ld4(g_hpad + o + FP + 4);
        conv_row_dualv(cxa0, cxa1, L_XZ + wo,      L_XR + wo,      az, ar);
        conv_row_dualv(cxb0, cxb1, L_XZ + wo + 20, L_XR + wo + 20, az, ar);
        conv_row_dualv(cha0, cha1, L_HZ + wo,      L_HR + wo,      az, ar);
        conv_row_dualv(chb0, chb1, L_HZ + wo + 20, L_HR + wo + 20, az, ar);
        wo += 40;
    }

    const bool lastfb = (fb == FBLK - 1);
#pragma unroll
    for (int p = 0; p < 4; ++p) {
        float zv[2][4], rv[2][4];
#pragma unroll
        for (int j = 0; j < 4; ++j) {
            float a, bb;
            upk(az[p][j], a, bb); zv[0][j] = sigf(a); zv[1][j] = sigf(bb);
            upk(ar[p][j], a, bb); rv[0][j] = sigf(a); rv[1][j] = sigf(bb);
        }
#pragma unroll
        for (int half = 0; half < 2; ++half) {
            const int co = 2 * p + half;
            const int ro = (b * C + co) * CH + (t + 1) * FP + 2 + f0;
            const float* hrow = g_hpad + ro;
            float* zrow  = g_z  + ro;
            float* rhrow = g_rh + ro;
            float2 h01 = *reinterpret_cast<const float2*>(hrow);
            float2 h23 = *reinterpret_cast<const float2*>(hrow + 2);
            st2(zrow,      zv[half][0], zv[half][1]);
            st2(zrow + 2,  zv[half][2], zv[half][3]);
            st2(rhrow,     rv[half][0] * h01.x, rv[half][1] * h01.y);
            st2(rhrow + 2, rv[half][2] * h23.x, rv[half][3] * h23.y);
            if (fb == 0) st2(rhrow - 2, 0.f, 0.f);
            if (lastfb) {
#pragma unroll
                for (int q = 4; q < 14; q += 2) st2(rhrow + q, 0.f, 0.f);
            }
        }
    }
}

// ---- K3: n + output (+L2 prefetch, (256,4) preserved) ----------------------------
__global__ void __launch_bounds__(256, 4) k3_out(float* __restrict__ out) {
    int g = blockIdx.x * 256 + threadIdx.x;
    if (g >= NTHREAD_MAIN) return;
    const int fb = g % FBLK; int r1 = g / FBLK;
    const int t = r1 % T, b = r1 / T;
    const int f0 = fb * 4;

    ULL an[4][4];
#pragma unroll
    for (int p = 0; p < 4; ++p) {
        ULL bn = c_wpk[L_BN + p];
#pragma unroll
        for (int j = 0; j < 4; ++j) an[p][j] = bn;
    }

    int o = (b * C) * CH + t * FP + f0;
    int wo = 0;
#pragma unroll 2
    for (int ci = 0; ci < C; ++ci) {
        const float* xr  = g_xp + o;
        const float* rhr = g_rh + o;
        // L2 prefetch of next iteration's rows (zero register cost; +CH slack)
        pf_l2(xr + CH);
        pf_l2(xr + CH + FP);
        pf_l2(rhr + CH);
        pf_l2(rhr + CH + FP);
        float4 xa0 = ld4(xr),       xa1 = ld4(xr + 4);
        float4 xb0 = ld4(xr + FP),  xb1 = ld4(xr + FP + 4);
        float4 ra0 = ld4(rhr),      ra1 = ld4(rhr + 4);
        float4 rb0 = ld4(rhr + FP), rb1 = ld4(rhr + FP + 4);
        conv_rowv(xa0, xa1, L_XN + wo,      an);
        conv_rowv(xb0, xb1, L_XN + wo + 20, an);
        conv_rowv(ra0, ra1, L_HN + wo,      an);
        conv_rowv(rb0, rb1, L_HN + wo + 20, an);
        o += CH; wo += 40;
    }

#pragma unroll
    for (int p = 0; p < 4; ++p) {
        float nv[2][4];
#pragma unroll
        for (int j = 0; j < 4; ++j) {
            float a, bb;
            upk(an[p][j], a, bb);
            nv[0][j] = tanh_fast(a); nv[1][j] = tanh_fast(bb);
        }
#pragma unroll
        for (int half = 0; half < 2; ++half) {
            const int co = 2 * p + half;
            const int ro = (b * C + co) * CH + (t + 1) * FP + 2 + f0;
            const float* zrow = g_z + ro;
            const float* hrow = g_hpad + ro;
            float* orow = out + (b * C + co) * (T * F) + t * F + f0;
            float2 z01 = *reinterpret_cast<const float2*>(zrow);
            float2 z23 = *reinterpret_cast<const float2*>(zrow + 2);
            float2 h01 = *reinterpret_cast<const float2*>(hrow);
            float2 h23 = *reinterpret_cast<const float2*>(hrow + 2);
            float zz[4] = {z01.x, z01.y, z23.x, z23.y};
            float hh[4] = {h01.x, h01.y, h23.x, h23.y};
#pragma unroll
            for (int j = 0; j < 4; ++j) {
                if (f0 + j < F)
                    orow[j] = (1.0f - zz[j]) * hh[j] + zz[j] * nv[half][j];
            }
        }
    }
}

// ---------------------------------------------------------------------------
extern "C" void kernel_launch(void* const* d_in, const int* in_sizes, int n_in,
                              void* d_out, int out_size)
{
    (void)in_sizes; (void)n_in; (void)out_size;
    const float* x = (const float*)d_in[0];
    const float* h = (const float*)d_in[1];

    static cudaStream_t s2 = nullptr;
    static cudaEvent_t evFork = nullptr, evJoin = nullptr;
    if (!s2) {
        cudaStreamCreateWithFlags(&s2, cudaStreamNonBlocking);
        cudaEventCreateWithFlags(&evFork, cudaEventDisableTiming);
        cudaEventCreateWithFlags(&evJoin, cudaEventDisableTiming);
    }

    prep_pack<<<(WPK_N + 255) / 256, 256>>>(
        (const float*)d_in[2],  (const float*)d_in[3],
        (const float*)d_in[4],  (const float*)d_in[5],
        (const float*)d_in[6],  (const float*)d_in[7],
        (const float*)d_in[8],  (const float*)d_in[9],
        (const float*)d_in[10], (const float*)d_in[11],
        (const float*)d_in[12], (const float*)d_in[13],
        (const float*)d_in[14], (const float*)d_in[15]);

    void* wsrc = nullptr;
    cudaGetSymbolAddress(&wsrc, g_wpk);
    cudaMemcpyToSymbolAsync(c_wpk, wsrc, WPK_N * sizeof(ULL), 0,
                            cudaMemcpyDeviceToDevice, 0);

    pad_x_k<<<(PAD_QX + 255) / 256, 256>>>(x);

    // fork: pad_h overlaps k1
    cudaEventRecord(evFork, 0);
    cudaStreamWaitEvent(s2, evFork, 0);
    pad_h_k<<<(PAD_QH + 255) / 256, 256, 0, s2>>>(h);
    cudaEventRecord(evJoin, s2);

    const int gmain = (NTHREAD_MAIN + 255) / 256;
    k1_pre<<<gmain, 256>>>();

    cudaStreamWaitEvent(0, evJoin, 0);
    k2_zr <<<gmain, 256>>>();
    k3_out<<<gmain, 256>>>((float*)d_out);
}